// round 11
// baseline (speedup 1.0000x reference)
#include <cuda_runtime.h>
#include <cuda_fp16.h>
#include <cstdint>

// Problem constants: B=2, L=2048, D=1024, H=16, hd=64
#define BB 2
#define LL 2048
#define DD 1024
#define NH 16
#define HD 64
#define ML (BB*LL)          // 4096 rows

// fp16 scratch
static __device__ __half g_xh[ML*DD];
static __device__ __half g_Qh[ML*DD];
static __device__ __half g_Kh[ML*DD];
static __device__ __half g_Vh[ML*DD];
static __device__ __half g_Ah[ML*DD];
static __device__ __half g_Wh[4*DD*DD];

// ---------------------------------------------------------------------------
// helpers
// ---------------------------------------------------------------------------
__device__ __forceinline__ uint32_t smem_u32(const void* p) {
    uint32_t a;
    asm("{ .reg .u64 t; cvta.to.shared.u64 t, %1; cvt.u32.u64 %0, t; }" : "=r"(a) : "l"(p));
    return a;
}

__device__ __forceinline__ uint32_t f2h2(float x, float y) {
    __half2 h = __floats2half2_rn(x, y);
    return *(uint32_t*)&h;
}

#define CPA16(dst, src) \
    asm volatile("cp.async.cg.shared.global [%0], [%1], 16;" :: "r"(dst), "l"(src))
#define CP_COMMIT() asm volatile("cp.async.commit_group;" ::: "memory")
#define CP_WAIT(n)  asm volatile("cp.async.wait_group %0;" :: "n"(n) : "memory")

#define LDSM4(r0,r1,r2,r3, addr) \
    asm volatile("ldmatrix.sync.aligned.m8n8.x4.shared.b16 {%0,%1,%2,%3}, [%4];" \
        : "=r"(r0),"=r"(r1),"=r"(r2),"=r"(r3) : "r"(addr))

#define LDSM4T(r0,r1,r2,r3, addr) \
    asm volatile("ldmatrix.sync.aligned.m8n8.x4.trans.shared.b16 {%0,%1,%2,%3}, [%4];" \
        : "=r"(r0),"=r"(r1),"=r"(r2),"=r"(r3) : "r"(addr))

__device__ __forceinline__ void mma16(float* c, const uint32_t* a, uint32_t b0, uint32_t b1) {
    asm volatile("mma.sync.aligned.m16n8k16.row.col.f32.f16.f16.f32 "
        "{%0,%1,%2,%3}, {%4,%5,%6,%7}, {%8,%9}, {%0,%1,%2,%3};"
        : "+f"(c[0]), "+f"(c[1]), "+f"(c[2]), "+f"(c[3])
        : "r"(a[0]), "r"(a[1]), "r"(a[2]), "r"(a[3]), "r"(b0), "r"(b1));
}

// ---------------------------------------------------------------------------
// Fused f32 -> f16 conversion of x (4M elems) + 4 weights (1M each).
// ---------------------------------------------------------------------------
__global__ void cvt_all(const float* __restrict__ x,
                        const float* __restrict__ Wq, const float* __restrict__ Wk,
                        const float* __restrict__ Wv, const float* __restrict__ Wo,
                        __half* __restrict__ xh, __half* __restrict__ Wh)
{
    int i = blockIdx.x * blockDim.x + threadIdx.x;     // float4 index, 0..2M-1
    int chunk = i >> 18;
    const float* in;
    __half* out;
    size_t base;
    if (chunk < 4) { in = x; out = xh; base = (size_t)i * 4; }
    else {
        int w = chunk - 4;
        in = (w == 0) ? Wq : (w == 1) ? Wk : (w == 2) ? Wv : Wo;
        out = Wh + (size_t)w * DD * DD;
        base = (size_t)(i & 0x3FFFF) * 4;
    }
    float4 v = *(const float4*)&in[base];
    __half2 h0 = __floats2half2_rn(v.x, v.y);
    __half2 h1 = __floats2half2_rn(v.z, v.w);
    *(uint2*)&out[base] = make_uint2(*(uint32_t*)&h0, *(uint32_t*)&h1);
}

// ---------------------------------------------------------------------------
// Pipelined FP16 GEMM: C[M,N] = A[M,K] @ W[N,K]^T, 128x128x64 tiles, 8 warps,
// cp.async 3-stage, ONE __syncthreads per chunk, loads 2 chunks ahead.
// MODE 0: fused QKV, RoPE in epilogue for z<2, fp16 out.
// MODE 1: f32 out (final projection).  Smem row stride 72 halves (144B).
// ---------------------------------------------------------------------------
#define BM 128
#define BN 128
#define BK 64
#define ALD 72
#define ATILE_B (BM*ALD*2)          // 18432 bytes
#define STAGE_B (2*ATILE_B)         // A + B = 36864 bytes
#define GEMM_SMEM (3*STAGE_B)       // 110592 bytes (2 CTA/SM: 221KB < 228KB)
#define NCH (DD/BK)                 // 16 chunks

template<int MODE>
__global__ __launch_bounds__(256) void gemm_f16p(
    const __half* __restrict__ A,
    const __half* __restrict__ Wa, const __half* __restrict__ Wb, const __half* __restrict__ Wc,
    __half* __restrict__ Qh, __half* __restrict__ Kh, __half* __restrict__ Vh,
    float* __restrict__ Cfin, const float* __restrict__ freqs)
{
    const int z = blockIdx.z;
    const __half* W = (z == 0) ? Wa : (z == 1) ? Wb : Wc;

    extern __shared__ char smem[];
    const uint32_t s0 = smem_u32(smem);

    const int tid  = threadIdx.x;
    const int lane = tid & 31, warp = tid >> 5;
    const int g = lane >> 2, t = lane & 3;
    const int lrow = lane & 15, lko = (lane >> 4) * 8;
    const int wm = (warp & 3) * 32;
    const int wn = (warp >> 2) * 64;
    const int row0 = blockIdx.y * BM, col0 = blockIdx.x * BN;

    // 2048 16B-chunks per stage (1024 A + 1024 B); 8 per thread
    auto load_stage = [&](int st, int k0) {
        uint32_t base = s0 + st * STAGE_B;
        #pragma unroll
        for (int i = 0; i < 4; i++) {
            int cid = tid + i * 256;          // 0..1023
            int r = cid >> 3, c8 = cid & 7;
            CPA16(base + r*144 + c8*16,           A + (size_t)(row0 + r) * DD + k0 + c8*8);
            CPA16(base + ATILE_B + r*144 + c8*16, W + (size_t)(col0 + r) * DD + k0 + c8*8);
        }
        CP_COMMIT();
    };

    float c[2][8][4] = {};

    load_stage(0, 0);
    load_stage(1, BK);

    for (int ch = 0; ch < NCH; ch++) {
        CP_WAIT(1);            // chunk ch resident
        __syncthreads();       // all warps done reading buffer (ch-1)%3
        if (ch + 2 < NCH) load_stage((ch + 2) % 3, (ch + 2) * BK);
        else CP_COMMIT();      // keep group accounting uniform

        const uint32_t ab = s0 + (ch % 3) * STAGE_B;
        const uint32_t bb = ab + ATILE_B;

        #pragma unroll
        for (int ks = 0; ks < 4; ks++) {
            const int kk = ks * 16;
            uint32_t af[2][4];
            #pragma unroll
            for (int mi = 0; mi < 2; mi++) {
                uint32_t ad = ab + (uint32_t)((wm + mi*16 + lrow) * ALD + kk + lko) * 2;
                LDSM4(af[mi][0], af[mi][1], af[mi][2], af[mi][3], ad);
            }
            #pragma unroll
            for (int n2 = 0; n2 < 4; n2++) {
                uint32_t r0, r1, r2, r3;
                uint32_t bd = bb + (uint32_t)((wn + n2*16 + lrow) * ALD + kk + lko) * 2;
                LDSM4(r0, r1, r2, r3, bd);
                #pragma unroll
                for (int mi = 0; mi < 2; mi++) {
                    mma16(c[mi][n2*2],   af[mi], r0, r2);
                    mma16(c[mi][n2*2+1], af[mi], r1, r3);
                }
            }
        }
    }

    #pragma unroll
    for (int mi = 0; mi < 2; mi++) {
        int r = row0 + wm + mi * 16 + g;
        #pragma unroll
        for (int ni = 0; ni < 8; ni++) {
            int cc = col0 + wn + (ni >> 1) * 16 + (ni & 1) * 8 + t * 2;
            float v0 = c[mi][ni][0], v1 = c[mi][ni][1];
            float v2 = c[mi][ni][2], v3 = c[mi][ni][3];
            if (MODE == 1) {
                *(float2*)&Cfin[(size_t)r * DD + cc]       = make_float2(v0, v1);
                *(float2*)&Cfin[(size_t)(r + 8) * DD + cc] = make_float2(v2, v3);
            } else if (z == 2) {
                *(__half2*)&Vh[(size_t)r * DD + cc]       = __floats2half2_rn(v0, v1);
                *(__half2*)&Vh[(size_t)(r + 8) * DD + cc] = __floats2half2_rn(v2, v3);
            } else {
                // fused RoPE: (v0,v1) is an adjacent (even,odd) pair within a head
                __half* C = z ? Kh : Qh;
                int pp = (cc & (HD - 1)) >> 1;
                int l0 = r & (LL - 1), l1 = (r + 8) & (LL - 1);
                float2 f0 = *(const float2*)&freqs[(l0 * (HD/2) + pp) * 2];
                float2 f1 = *(const float2*)&freqs[(l1 * (HD/2) + pp) * 2];
                *(__half2*)&C[(size_t)r * DD + cc] =
                    __floats2half2_rn(v0*f0.x - v1*f0.y, v0*f0.y + v1*f0.x);
                *(__half2*)&C[(size_t)(r + 8) * DD + cc] =
                    __floats2half2_rn(v2*f1.x - v3*f1.y, v2*f1.y + v3*f1.x);
            }
        }
    }
}

// ---------------------------------------------------------------------------
// Flash attention (causal), FA2-style register-resident softmax (R9 shape).
// BQ=128, kv-tile 64. 8 warps; warp w owns q-rows w*16..w*16+15, ALL 64 kv.
// ---------------------------------------------------------------------------
#define BQ 128
#define HLD 72
#define QB  (BQ*HLD*2)           // Q tile bytes
#define KVB (64*HLD*2)           // one K or V buffer bytes
#define FL_SMEM_BYTES (QB + 4*KVB)

__global__ __launch_bounds__(256) void flash_f16(
    const __half* __restrict__ Q, const __half* __restrict__ K,
    const __half* __restrict__ V, __half* __restrict__ O)
{
    extern __shared__ __half hsm[];
    const uint32_t qsm  = smem_u32(hsm);
    const uint32_t ksm0 = qsm + QB;           // K0, K1, V0, V1
    const uint32_t vsm0 = qsm + QB + 2*KVB;

    const int tid = threadIdx.x;
    const int lane = tid & 31, warp = tid >> 5;
    const int g = lane >> 2, t = lane & 3;
    const int lrow = lane & 15, lko = (lane >> 4) * 8;
    const int wr = warp * 16;                 // this warp's q-row block
    const int b = blockIdx.y >> 4, h = blockIdx.y & 15;
    const int qi = (int)gridDim.x - 1 - (int)blockIdx.x;   // heavy blocks first
    const int q0 = qi * BQ;
    const size_t headoff = (size_t)b * LL * DD + (size_t)h * HD;

    auto issue_kv = [&](int kt, int buf) {
        const int kv0 = kt * 64;
        uint32_t kb = ksm0 + buf * KVB;
        uint32_t vb = vsm0 + buf * KVB;
        #pragma unroll
        for (int i = 0; i < 4; i++) {
            int cid = tid + i * 256;          // 0..1023
            int isv = cid >> 9;
            int cc  = cid & 511;
            int r = cc >> 3, c8 = cc & 7;
            const __half* src = (isv ? V : K) + headoff + (size_t)(kv0 + r) * DD + c8*8;
            CPA16((isv ? vb : kb) + r*144 + c8*16, src);
        }
    };

    // group 0: Q tile (128 rows) + kv tile 0;  group 1: kv tile 1
    #pragma unroll
    for (int i = 0; i < 4; i++) {
        int cid = tid + i * 256;              // 0..1023
        int r = cid >> 3, c8 = cid & 7;
        CPA16(qsm + r*144 + c8*16, Q + headoff + (size_t)(q0 + r) * DD + c8*8);
    }
    issue_kv(0, 0);
    CP_COMMIT();
    const int ntiles = 2 * qi + 2;
    issue_kv(1, 1);
    CP_COMMIT();

    uint32_t qf[4][4];
    float acc[8][4] = {};
    float m0 = -1e30f, m1 = -1e30f, l0 = 0.f, l1 = 0.f;

    for (int kt = 0; kt < ntiles; kt++) {
        const int kv0 = kt * 64;
        const uint32_t kb = ksm0 + (kt & 1) * KVB;
        const uint32_t vb = vsm0 + (kt & 1) * KVB;
        CP_WAIT(1);
        __syncthreads();

        if (kt == 0) {
            #pragma unroll
            for (int ks = 0; ks < 4; ks++)
                LDSM4(qf[ks][0], qf[ks][1], qf[ks][2], qf[ks][3],
                      qsm + (uint32_t)((wr + lrow) * HLD + ks*16 + lko) * 2);
        }

        // skip warps whose 16 rows are entirely masked (last tile, rows < 64)
        if (!(kt == ntiles - 1 && wr < 64)) {
            // S = Q @ K^T : warp computes 16 x 64
            float sf[8][4] = {};
            #pragma unroll
            for (int ks = 0; ks < 4; ks++) {
                #pragma unroll
                for (int ng = 0; ng < 4; ng++) {
                    uint32_t r0, r1, r2, r3;
                    LDSM4(r0, r1, r2, r3,
                          kb + (uint32_t)((ng*16 + lrow) * HLD + ks*16 + lko) * 2);
                    mma16(sf[ng*2],   qf[ks], r0, r2);
                    mma16(sf[ng*2+1], qf[ks], r1, r3);
                }
            }
            // scale + causal mask (only the 2 diagonal tiles need it)
            const int gr0 = q0 + wr + g, gr1 = gr0 + 8;
            if (kt >= ntiles - 2) {
                #pragma unroll
                for (int nb = 0; nb < 8; nb++) {
                    int gc = kv0 + nb*8 + t*2;
                    sf[nb][0] = (gc     > gr0) ? -1e30f : sf[nb][0]*0.125f;
                    sf[nb][1] = (gc + 1 > gr0) ? -1e30f : sf[nb][1]*0.125f;
                    sf[nb][2] = (gc     > gr1) ? -1e30f : sf[nb][2]*0.125f;
                    sf[nb][3] = (gc + 1 > gr1) ? -1e30f : sf[nb][3]*0.125f;
                }
            } else {
                #pragma unroll
                for (int nb = 0; nb < 8; nb++) {
                    sf[nb][0] *= 0.125f; sf[nb][1] *= 0.125f;
                    sf[nb][2] *= 0.125f; sf[nb][3] *= 0.125f;
                }
            }
            // register-resident online softmax (rows g and g+8)
            float rmx0 = -1e30f, rmx1 = -1e30f;
            #pragma unroll
            for (int nb = 0; nb < 8; nb++) {
                rmx0 = fmaxf(rmx0, fmaxf(sf[nb][0], sf[nb][1]));
                rmx1 = fmaxf(rmx1, fmaxf(sf[nb][2], sf[nb][3]));
            }
            rmx0 = fmaxf(rmx0, __shfl_xor_sync(0xffffffffu, rmx0, 1));
            rmx0 = fmaxf(rmx0, __shfl_xor_sync(0xffffffffu, rmx0, 2));
            rmx1 = fmaxf(rmx1, __shfl_xor_sync(0xffffffffu, rmx1, 1));
            rmx1 = fmaxf(rmx1, __shfl_xor_sync(0xffffffffu, rmx1, 2));
            float nm0 = fmaxf(m0, rmx0), nm1 = fmaxf(m1, rmx1);
            float al0 = __expf(m0 - nm0), al1 = __expf(m1 - nm1);
            m0 = nm0; m1 = nm1;
            float s0 = 0.f, s1 = 0.f;
            #pragma unroll
            for (int nb = 0; nb < 8; nb++) {
                sf[nb][0] = __expf(sf[nb][0] - nm0); s0 += sf[nb][0];
                sf[nb][1] = __expf(sf[nb][1] - nm0); s0 += sf[nb][1];
                sf[nb][2] = __expf(sf[nb][2] - nm1); s1 += sf[nb][2];
                sf[nb][3] = __expf(sf[nb][3] - nm1); s1 += sf[nb][3];
            }
            s0 += __shfl_xor_sync(0xffffffffu, s0, 1);
            s0 += __shfl_xor_sync(0xffffffffu, s0, 2);
            s1 += __shfl_xor_sync(0xffffffffu, s1, 1);
            s1 += __shfl_xor_sync(0xffffffffu, s1, 2);
            l0 = l0 * al0 + s0;
            l1 = l1 * al1 + s1;
            #pragma unroll
            for (int nb = 0; nb < 8; nb++) {
                acc[nb][0] *= al0; acc[nb][1] *= al0;
                acc[nb][2] *= al1; acc[nb][3] *= al1;
            }
            // O += P @ V  (P packed from S fragments, no smem)
            #pragma unroll
            for (int ks = 0; ks < 4; ks++) {
                uint32_t pf[4];
                pf[0] = f2h2(sf[2*ks][0],   sf[2*ks][1]);
                pf[1] = f2h2(sf[2*ks][2],   sf[2*ks][3]);
                pf[2] = f2h2(sf[2*ks+1][0], sf[2*ks+1][1]);
                pf[3] = f2h2(sf[2*ks+1][2], sf[2*ks+1][3]);
                #pragma unroll
                for (int ng = 0; ng < 4; ng++) {
                    uint32_t r0, r1, r2, r3;   // trans: rows = kv, cols = hd
                    LDSM4T(r0, r1, r2, r3,
                           vb + (uint32_t)((ks*16 + lrow) * HLD + ng*16 + lko) * 2);
                    mma16(acc[ng*2],   pf, r0, r1);
                    mma16(acc[ng*2+1], pf, r2, r3);
                }
            }
        }

        __syncthreads();
        if (kt + 2 < ntiles) issue_kv(kt + 2, kt & 1);
        CP_COMMIT();
    }

    // epilogue (fp16 out)
    {
        int r0r = q0 + wr + g, r1 = r0r + 8;
        float inv0 = 1.f / l0, inv1 = 1.f / l1;
        #pragma unroll
        for (int nb = 0; nb < 8; nb++) {
            int cc = nb*8 + t*2;
            *(__half2*)&O[headoff + (size_t)r0r*DD + cc] =
                __floats2half2_rn(acc[nb][0]*inv0, acc[nb][1]*inv0);
            *(__half2*)&O[headoff + (size_t)r1*DD + cc] =
                __floats2half2_rn(acc[nb][2]*inv1, acc[nb][3]*inv1);
        }
    }
}

// ---------------------------------------------------------------------------
extern "C" void kernel_launch(void* const* d_in, const int* in_sizes, int n_in,
                              void* d_out, int out_size)
{
    const float* x     = (const float*)d_in[0];
    const float* freqs = (const float*)d_in[1];
    // d_in[2] = attention_mask (pure causal; handled structurally)
    const float* Wq = (const float*)d_in[3];
    const float* Wk = (const float*)d_in[4];
    const float* Wv = (const float*)d_in[5];
    const float* Wo = (const float*)d_in[6];
    float* out = (float*)d_out;

    __half *pxh, *pQh, *pKh, *pVh, *pAh, *pWh;
    cudaGetSymbolAddress((void**)&pxh, g_xh);
    cudaGetSymbolAddress((void**)&pQh, g_Qh);
    cudaGetSymbolAddress((void**)&pKh, g_Kh);
    cudaGetSymbolAddress((void**)&pVh, g_Vh);
    cudaGetSymbolAddress((void**)&pAh, g_Ah);
    cudaGetSymbolAddress((void**)&pWh, g_Wh);

    // fused f32 -> f16 conversions (x + 4 weights)
    cvt_all<<<(2*ML*DD/4)/256, 256>>>(x, Wq, Wk, Wv, Wo, pxh, pWh);

    cudaFuncSetAttribute(gemm_f16p<0>, cudaFuncAttributeMaxDynamicSharedMemorySize, GEMM_SMEM);
    cudaFuncSetAttribute(gemm_f16p<1>, cudaFuncAttributeMaxDynamicSharedMemorySize, GEMM_SMEM);

    // Fused QKV projections with RoPE in epilogue (z0->Qh, z1->Kh, z2->Vh)
    gemm_f16p<0><<<dim3(DD/BN, ML/BM, 3), 256, GEMM_SMEM>>>(
        pxh, pWh, pWh + DD*DD, pWh + 2*DD*DD, pQh, pKh, pVh, nullptr, freqs);

    cudaFuncSetAttribute(flash_f16, cudaFuncAttributeMaxDynamicSharedMemorySize, FL_SMEM_BYTES);
    flash_f16<<<dim3(LL/BQ, BB*NH), 256, FL_SMEM_BYTES>>>(pQh, pKh, pVh, pAh);

    // Output projection: f16 A @ Wo^T -> f32 out
    gemm_f16p<1><<<dim3(DD/BN, ML/BM, 1), 256, GEMM_SMEM>>>(
        pAh, pWh + 3*DD*DD, nullptr, nullptr, nullptr, nullptr, nullptr, out, nullptr);
}

// round 12
// speedup vs baseline: 1.5295x; 1.5295x over previous
#include <cuda_runtime.h>
#include <cuda_fp16.h>
#include <cstdint>

// Problem constants: B=2, L=2048, D=1024, H=16, hd=64
#define BB 2
#define LL 2048
#define DD 1024
#define NH 16
#define HD 64
#define ML (BB*LL)          // 4096 rows

// fp16 scratch
static __device__ __half g_xh[ML*DD];
static __device__ __half g_Qh[ML*DD];
static __device__ __half g_Kh[ML*DD];
static __device__ __half g_Vh[ML*DD];
static __device__ __half g_Ah[ML*DD];
static __device__ __half g_Wh[4*DD*DD];

// ---------------------------------------------------------------------------
// helpers
// ---------------------------------------------------------------------------
__device__ __forceinline__ uint32_t smem_u32(const void* p) {
    uint32_t a;
    asm("{ .reg .u64 t; cvta.to.shared.u64 t, %1; cvt.u32.u64 %0, t; }" : "=r"(a) : "l"(p));
    return a;
}

__device__ __forceinline__ uint32_t f2h2(float x, float y) {
    __half2 h = __floats2half2_rn(x, y);
    return *(uint32_t*)&h;
}

#define CPA16(dst, src) \
    asm volatile("cp.async.cg.shared.global [%0], [%1], 16;" :: "r"(dst), "l"(src))
#define CP_COMMIT() asm volatile("cp.async.commit_group;" ::: "memory")
#define CP_WAIT(n)  asm volatile("cp.async.wait_group %0;" :: "n"(n) : "memory")

#define LDSM4(r0,r1,r2,r3, addr) \
    asm volatile("ldmatrix.sync.aligned.m8n8.x4.shared.b16 {%0,%1,%2,%3}, [%4];" \
        : "=r"(r0),"=r"(r1),"=r"(r2),"=r"(r3) : "r"(addr))

#define LDSM4T(r0,r1,r2,r3, addr) \
    asm volatile("ldmatrix.sync.aligned.m8n8.x4.trans.shared.b16 {%0,%1,%2,%3}, [%4];" \
        : "=r"(r0),"=r"(r1),"=r"(r2),"=r"(r3) : "r"(addr))

__device__ __forceinline__ void mma16(float* c, const uint32_t* a, uint32_t b0, uint32_t b1) {
    asm volatile("mma.sync.aligned.m16n8k16.row.col.f32.f16.f16.f32 "
        "{%0,%1,%2,%3}, {%4,%5,%6,%7}, {%8,%9}, {%0,%1,%2,%3};"
        : "+f"(c[0]), "+f"(c[1]), "+f"(c[2]), "+f"(c[3])
        : "r"(a[0]), "r"(a[1]), "r"(a[2]), "r"(a[3]), "r"(b0), "r"(b1));
}

// ---------------------------------------------------------------------------
// Fused f32 -> f16 conversion of x (4M elems) + 4 weights (1M each).
// ---------------------------------------------------------------------------
__global__ void cvt_all(const float* __restrict__ x,
                        const float* __restrict__ Wq, const float* __restrict__ Wk,
                        const float* __restrict__ Wv, const float* __restrict__ Wo,
                        __half* __restrict__ xh, __half* __restrict__ Wh)
{
    int i = blockIdx.x * blockDim.x + threadIdx.x;     // float4 index, 0..2M-1
    int chunk = i >> 18;
    const float* in;
    __half* out;
    size_t base;
    if (chunk < 4) { in = x; out = xh; base = (size_t)i * 4; }
    else {
        int w = chunk - 4;
        in = (w == 0) ? Wq : (w == 1) ? Wk : (w == 2) ? Wv : Wo;
        out = Wh + (size_t)w * DD * DD;
        base = (size_t)(i & 0x3FFFF) * 4;
    }
    float4 v = *(const float4*)&in[base];
    __half2 h0 = __floats2half2_rn(v.x, v.y);
    __half2 h1 = __floats2half2_rn(v.z, v.w);
    *(uint2*)&out[base] = make_uint2(*(uint32_t*)&h0, *(uint32_t*)&h1);
}

// ---------------------------------------------------------------------------
// Pipelined FP16 GEMM: C[M,N] = A[M,K] @ W[N,K]^T, 128x128x64 tiles, 8 warps,
// cp.async 2-stage (R10-proven cadence: wait->sync->MMA->sync->load), with
// B-fragment double-buffering inside each k-step (LDSM n2+1 issued before the
// MMAs of n2, hiding LDSM latency behind the MMA burst).
// MODE 0: fused QKV, RoPE in epilogue for z<2, fp16 out.  MODE 1: f32 out.
// ---------------------------------------------------------------------------
#define BM 128
#define BN 128
#define BK 64
#define ALD 72
#define ATILE_B (BM*ALD*2)          // 18432 bytes
#define STAGE_B (2*ATILE_B)         // A + B = 36864 bytes
#define GEMM_SMEM (2*STAGE_B)       // 73728 bytes
#define NCH (DD/BK)                 // 16 chunks

template<int MODE>
__global__ __launch_bounds__(256, 2) void gemm_f16p(
    const __half* __restrict__ A,
    const __half* __restrict__ Wa, const __half* __restrict__ Wb, const __half* __restrict__ Wc,
    __half* __restrict__ Qh, __half* __restrict__ Kh, __half* __restrict__ Vh,
    float* __restrict__ Cfin, const float* __restrict__ freqs)
{
    const int z = blockIdx.z;
    const __half* W = (z == 0) ? Wa : (z == 1) ? Wb : Wc;

    extern __shared__ char smem[];
    const uint32_t s0 = smem_u32(smem);

    const int tid  = threadIdx.x;
    const int lane = tid & 31, warp = tid >> 5;
    const int g = lane >> 2, t = lane & 3;
    const int lrow = lane & 15, lko = (lane >> 4) * 8;
    const int wm = (warp & 3) * 32;
    const int wn = (warp >> 2) * 64;
    const int row0 = blockIdx.y * BM, col0 = blockIdx.x * BN;

    // 2048 16B-chunks per stage (1024 A + 1024 B); 8 per thread
    auto load_stage = [&](int st, int k0) {
        uint32_t base = s0 + st * STAGE_B;
        #pragma unroll
        for (int i = 0; i < 4; i++) {
            int cid = tid + i * 256;          // 0..1023
            int r = cid >> 3, c8 = cid & 7;
            CPA16(base + r*144 + c8*16,           A + (size_t)(row0 + r) * DD + k0 + c8*8);
            CPA16(base + ATILE_B + r*144 + c8*16, W + (size_t)(col0 + r) * DD + k0 + c8*8);
        }
        CP_COMMIT();
    };

    float c[2][8][4] = {};

    load_stage(0, 0);
    load_stage(1, BK);

    for (int ch = 0; ch < NCH; ch++) {
        CP_WAIT(1);
        __syncthreads();

        const uint32_t ab = s0 + (ch & 1) * STAGE_B;
        const uint32_t bb = ab + ATILE_B;

        #pragma unroll
        for (int ks = 0; ks < 4; ks++) {
            const int kk = ks * 16;
            uint32_t af[2][4];
            #pragma unroll
            for (int mi = 0; mi < 2; mi++) {
                uint32_t ad = ab + (uint32_t)((wm + mi*16 + lrow) * ALD + kk + lko) * 2;
                LDSM4(af[mi][0], af[mi][1], af[mi][2], af[mi][3], ad);
            }
            // B-fragment double buffer: LDSM for n2+1 before MMAs of n2
            uint32_t bf[2][4];
            LDSM4(bf[0][0], bf[0][1], bf[0][2], bf[0][3],
                  bb + (uint32_t)((wn + lrow) * ALD + kk + lko) * 2);
            #pragma unroll
            for (int n2 = 0; n2 < 4; n2++) {
                if (n2 < 3) {
                    uint32_t bd = bb + (uint32_t)((wn + (n2+1)*16 + lrow) * ALD + kk + lko) * 2;
                    LDSM4(bf[(n2+1)&1][0], bf[(n2+1)&1][1],
                          bf[(n2+1)&1][2], bf[(n2+1)&1][3], bd);
                }
                const uint32_t* b = bf[n2 & 1];
                #pragma unroll
                for (int mi = 0; mi < 2; mi++) {
                    mma16(c[mi][n2*2],   af[mi], b[0], b[2]);
                    mma16(c[mi][n2*2+1], af[mi], b[1], b[3]);
                }
            }
        }
        __syncthreads();
        if (ch + 2 < NCH) load_stage(ch & 1, (ch + 2) * BK);
        else CP_COMMIT();
    }

    #pragma unroll
    for (int mi = 0; mi < 2; mi++) {
        int r = row0 + wm + mi * 16 + g;
        #pragma unroll
        for (int ni = 0; ni < 8; ni++) {
            int cc = col0 + wn + (ni >> 1) * 16 + (ni & 1) * 8 + t * 2;
            float v0 = c[mi][ni][0], v1 = c[mi][ni][1];
            float v2 = c[mi][ni][2], v3 = c[mi][ni][3];
            if (MODE == 1) {
                *(float2*)&Cfin[(size_t)r * DD + cc]       = make_float2(v0, v1);
                *(float2*)&Cfin[(size_t)(r + 8) * DD + cc] = make_float2(v2, v3);
            } else if (z == 2) {
                *(__half2*)&Vh[(size_t)r * DD + cc]       = __floats2half2_rn(v0, v1);
                *(__half2*)&Vh[(size_t)(r + 8) * DD + cc] = __floats2half2_rn(v2, v3);
            } else {
                // fused RoPE: (v0,v1) is an adjacent (even,odd) pair within a head
                __half* C = z ? Kh : Qh;
                int pp = (cc & (HD - 1)) >> 1;
                int l0 = r & (LL - 1), l1 = (r + 8) & (LL - 1);
                float2 f0 = *(const float2*)&freqs[(l0 * (HD/2) + pp) * 2];
                float2 f1 = *(const float2*)&freqs[(l1 * (HD/2) + pp) * 2];
                *(__half2*)&C[(size_t)r * DD + cc] =
                    __floats2half2_rn(v0*f0.x - v1*f0.y, v0*f0.y + v1*f0.x);
                *(__half2*)&C[(size_t)(r + 8) * DD + cc] =
                    __floats2half2_rn(v2*f1.x - v3*f1.y, v2*f1.y + v3*f1.x);
            }
        }
    }
}

// ---------------------------------------------------------------------------
// Flash attention (causal), FA2-style register-resident softmax (R9 shape).
// BQ=128, kv-tile 64. 8 warps; warp w owns q-rows w*16..w*16+15, ALL 64 kv.
// ---------------------------------------------------------------------------
#define BQ 128
#define HLD 72
#define QB  (BQ*HLD*2)           // Q tile bytes
#define KVB (64*HLD*2)           // one K or V buffer bytes
#define FL_SMEM_BYTES (QB + 4*KVB)

__global__ __launch_bounds__(256) void flash_f16(
    const __half* __restrict__ Q, const __half* __restrict__ K,
    const __half* __restrict__ V, __half* __restrict__ O)
{
    extern __shared__ __half hsm[];
    const uint32_t qsm  = smem_u32(hsm);
    const uint32_t ksm0 = qsm + QB;           // K0, K1, V0, V1
    const uint32_t vsm0 = qsm + QB + 2*KVB;

    const int tid = threadIdx.x;
    const int lane = tid & 31, warp = tid >> 5;
    const int g = lane >> 2, t = lane & 3;
    const int lrow = lane & 15, lko = (lane >> 4) * 8;
    const int wr = warp * 16;                 // this warp's q-row block
    const int b = blockIdx.y >> 4, h = blockIdx.y & 15;
    const int qi = (int)gridDim.x - 1 - (int)blockIdx.x;   // heavy blocks first
    const int q0 = qi * BQ;
    const size_t headoff = (size_t)b * LL * DD + (size_t)h * HD;

    auto issue_kv = [&](int kt, int buf) {
        const int kv0 = kt * 64;
        uint32_t kb = ksm0 + buf * KVB;
        uint32_t vb = vsm0 + buf * KVB;
        #pragma unroll
        for (int i = 0; i < 4; i++) {
            int cid = tid + i * 256;          // 0..1023
            int isv = cid >> 9;
            int cc  = cid & 511;
            int r = cc >> 3, c8 = cc & 7;
            const __half* src = (isv ? V : K) + headoff + (size_t)(kv0 + r) * DD + c8*8;
            CPA16((isv ? vb : kb) + r*144 + c8*16, src);
        }
    };

    // group 0: Q tile (128 rows) + kv tile 0;  group 1: kv tile 1
    #pragma unroll
    for (int i = 0; i < 4; i++) {
        int cid = tid + i * 256;              // 0..1023
        int r = cid >> 3, c8 = cid & 7;
        CPA16(qsm + r*144 + c8*16, Q + headoff + (size_t)(q0 + r) * DD + c8*8);
    }
    issue_kv(0, 0);
    CP_COMMIT();
    const int ntiles = 2 * qi + 2;
    issue_kv(1, 1);
    CP_COMMIT();

    uint32_t qf[4][4];
    float acc[8][4] = {};
    float m0 = -1e30f, m1 = -1e30f, l0 = 0.f, l1 = 0.f;

    for (int kt = 0; kt < ntiles; kt++) {
        const int kv0 = kt * 64;
        const uint32_t kb = ksm0 + (kt & 1) * KVB;
        const uint32_t vb = vsm0 + (kt & 1) * KVB;
        CP_WAIT(1);
        __syncthreads();

        if (kt == 0) {
            #pragma unroll
            for (int ks = 0; ks < 4; ks++)
                LDSM4(qf[ks][0], qf[ks][1], qf[ks][2], qf[ks][3],
                      qsm + (uint32_t)((wr + lrow) * HLD + ks*16 + lko) * 2);
        }

        // skip warps whose 16 rows are entirely masked (last tile, rows < 64)
        if (!(kt == ntiles - 1 && wr < 64)) {
            // S = Q @ K^T : warp computes 16 x 64
            float sf[8][4] = {};
            #pragma unroll
            for (int ks = 0; ks < 4; ks++) {
                #pragma unroll
                for (int ng = 0; ng < 4; ng++) {
                    uint32_t r0, r1, r2, r3;
                    LDSM4(r0, r1, r2, r3,
                          kb + (uint32_t)((ng*16 + lrow) * HLD + ks*16 + lko) * 2);
                    mma16(sf[ng*2],   qf[ks], r0, r2);
                    mma16(sf[ng*2+1], qf[ks], r1, r3);
                }
            }
            // scale + causal mask (only the 2 diagonal tiles need it)
            const int gr0 = q0 + wr + g, gr1 = gr0 + 8;
            if (kt >= ntiles - 2) {
                #pragma unroll
                for (int nb = 0; nb < 8; nb++) {
                    int gc = kv0 + nb*8 + t*2;
                    sf[nb][0] = (gc     > gr0) ? -1e30f : sf[nb][0]*0.125f;
                    sf[nb][1] = (gc + 1 > gr0) ? -1e30f : sf[nb][1]*0.125f;
                    sf[nb][2] = (gc     > gr1) ? -1e30f : sf[nb][2]*0.125f;
                    sf[nb][3] = (gc + 1 > gr1) ? -1e30f : sf[nb][3]*0.125f;
                }
            } else {
                #pragma unroll
                for (int nb = 0; nb < 8; nb++) {
                    sf[nb][0] *= 0.125f; sf[nb][1] *= 0.125f;
                    sf[nb][2] *= 0.125f; sf[nb][3] *= 0.125f;
                }
            }
            // register-resident online softmax (rows g and g+8)
            float rmx0 = -1e30f, rmx1 = -1e30f;
            #pragma unroll
            for (int nb = 0; nb < 8; nb++) {
                rmx0 = fmaxf(rmx0, fmaxf(sf[nb][0], sf[nb][1]));
                rmx1 = fmaxf(rmx1, fmaxf(sf[nb][2], sf[nb][3]));
            }
            rmx0 = fmaxf(rmx0, __shfl_xor_sync(0xffffffffu, rmx0, 1));
            rmx0 = fmaxf(rmx0, __shfl_xor_sync(0xffffffffu, rmx0, 2));
            rmx1 = fmaxf(rmx1, __shfl_xor_sync(0xffffffffu, rmx1, 1));
            rmx1 = fmaxf(rmx1, __shfl_xor_sync(0xffffffffu, rmx1, 2));
            float nm0 = fmaxf(m0, rmx0), nm1 = fmaxf(m1, rmx1);
            float al0 = __expf(m0 - nm0), al1 = __expf(m1 - nm1);
            m0 = nm0; m1 = nm1;
            float s0 = 0.f, s1 = 0.f;
            #pragma unroll
            for (int nb = 0; nb < 8; nb++) {
                sf[nb][0] = __expf(sf[nb][0] - nm0); s0 += sf[nb][0];
                sf[nb][1] = __expf(sf[nb][1] - nm0); s0 += sf[nb][1];
                sf[nb][2] = __expf(sf[nb][2] - nm1); s1 += sf[nb][2];
                sf[nb][3] = __expf(sf[nb][3] - nm1); s1 += sf[nb][3];
            }
            s0 += __shfl_xor_sync(0xffffffffu, s0, 1);
            s0 += __shfl_xor_sync(0xffffffffu, s0, 2);
            s1 += __shfl_xor_sync(0xffffffffu, s1, 1);
            s1 += __shfl_xor_sync(0xffffffffu, s1, 2);
            l0 = l0 * al0 + s0;
            l1 = l1 * al1 + s1;
            #pragma unroll
            for (int nb = 0; nb < 8; nb++) {
                acc[nb][0] *= al0; acc[nb][1] *= al0;
                acc[nb][2] *= al1; acc[nb][3] *= al1;
            }
            // O += P @ V  (P packed from S fragments, no smem)
            #pragma unroll
            for (int ks = 0; ks < 4; ks++) {
                uint32_t pf[4];
                pf[0] = f2h2(sf[2*ks][0],   sf[2*ks][1]);
                pf[1] = f2h2(sf[2*ks][2],   sf[2*ks][3]);
                pf[2] = f2h2(sf[2*ks+1][0], sf[2*ks+1][1]);
                pf[3] = f2h2(sf[2*ks+1][2], sf[2*ks+1][3]);
                #pragma unroll
                for (int ng = 0; ng < 4; ng++) {
                    uint32_t r0, r1, r2, r3;   // trans: rows = kv, cols = hd
                    LDSM4T(r0, r1, r2, r3,
                           vb + (uint32_t)((ks*16 + lrow) * HLD + ng*16 + lko) * 2);
                    mma16(acc[ng*2],   pf, r0, r1);
                    mma16(acc[ng*2+1], pf, r2, r3);
                }
            }
        }

        __syncthreads();
        if (kt + 2 < ntiles) issue_kv(kt + 2, kt & 1);
        CP_COMMIT();
    }

    // epilogue (fp16 out)
    {
        int r0r = q0 + wr + g, r1 = r0r + 8;
        float inv0 = 1.f / l0, inv1 = 1.f / l1;
        #pragma unroll
        for (int nb = 0; nb < 8; nb++) {
            int cc = nb*8 + t*2;
            *(__half2*)&O[headoff + (size_t)r0r*DD + cc] =
                __floats2half2_rn(acc[nb][0]*inv0, acc[nb][1]*inv0);
            *(__half2*)&O[headoff + (size_t)r1*DD + cc] =
                __floats2half2_rn(acc[nb][2]*inv1, acc[nb][3]*inv1);
        }
    }
}

// ---------------------------------------------------------------------------
extern "C" void kernel_launch(void* const* d_in, const int* in_sizes, int n_in,
                              void* d_out, int out_size)
{
    const float* x     = (const float*)d_in[0];
    const float* freqs = (const float*)d_in[1];
    // d_in[2] = attention_mask (pure causal; handled structurally)
    const float* Wq = (const float*)d_in[3];
    const float* Wk = (const float*)d_in[4];
    const float* Wv = (const float*)d_in[5];
    const float* Wo = (const float*)d_in[6];
    float* out = (float*)d_out;

    __half *pxh, *pQh, *pKh, *pVh, *pAh, *pWh;
    cudaGetSymbolAddress((void**)&pxh, g_xh);
    cudaGetSymbolAddress((void**)&pQh, g_Qh);
    cudaGetSymbolAddress((void**)&pKh, g_Kh);
    cudaGetSymbolAddress((void**)&pVh, g_Vh);
    cudaGetSymbolAddress((void**)&pAh, g_Ah);
    cudaGetSymbolAddress((void**)&pWh, g_Wh);

    // fused f32 -> f16 conversions (x + 4 weights)
    cvt_all<<<(2*ML*DD/4)/256, 256>>>(x, Wq, Wk, Wv, Wo, pxh, pWh);

    cudaFuncSetAttribute(gemm_f16p<0>, cudaFuncAttributeMaxDynamicSharedMemorySize, GEMM_SMEM);
    cudaFuncSetAttribute(gemm_f16p<1>, cudaFuncAttributeMaxDynamicSharedMemorySize, GEMM_SMEM);

    // Fused QKV projections with RoPE in epilogue (z0->Qh, z1->Kh, z2->Vh)
    gemm_f16p<0><<<dim3(DD/BN, ML/BM, 3), 256, GEMM_SMEM>>>(
        pxh, pWh, pWh + DD*DD, pWh + 2*DD*DD, pQh, pKh, pVh, nullptr, freqs);

    cudaFuncSetAttribute(flash_f16, cudaFuncAttributeMaxDynamicSharedMemorySize, FL_SMEM_BYTES);
    flash_f16<<<dim3(LL/BQ, BB*NH), 256, FL_SMEM_BYTES>>>(pQh, pKh, pVh, pAh);

    // Output projection: f16 A @ Wo^T -> f32 out
    gemm_f16p<1><<<dim3(DD/BN, ML/BM, 1), 256, GEMM_SMEM>>>(
        pAh, pWh + 3*DD*DD, nullptr, nullptr, nullptr, nullptr, nullptr, out, nullptr);
}

// round 13
// speedup vs baseline: 1.5796x; 1.0328x over previous
#include <cuda_runtime.h>
#include <cuda_fp16.h>
#include <cstdint>

// Problem constants: B=2, L=2048, D=1024, H=16, hd=64
#define BB 2
#define LL 2048
#define DD 1024
#define NH 16
#define HD 64
#define ML (BB*LL)          // 4096 rows

// fp16 scratch
static __device__ __half g_xh[ML*DD];
static __device__ __half g_Qh[ML*DD];
static __device__ __half g_Kh[ML*DD];
static __device__ __half g_Vh[ML*DD];
static __device__ __half g_Ah[ML*DD];
static __device__ __half g_Wh[4*DD*DD];

// ---------------------------------------------------------------------------
// helpers
// ---------------------------------------------------------------------------
__device__ __forceinline__ uint32_t smem_u32(const void* p) {
    uint32_t a;
    asm("{ .reg .u64 t; cvta.to.shared.u64 t, %1; cvt.u32.u64 %0, t; }" : "=r"(a) : "l"(p));
    return a;
}

__device__ __forceinline__ uint32_t f2h2(float x, float y) {
    __half2 h = __floats2half2_rn(x, y);
    return *(uint32_t*)&h;
}

// two fp16 exp2's in ONE MUFU op
__device__ __forceinline__ uint32_t h2exp2(uint32_t a) {
    uint32_t d;
    asm("ex2.approx.f16x2 %0, %1;" : "=r"(d) : "r"(a));
    return d;
}

#define CPA16(dst, src) \
    asm volatile("cp.async.cg.shared.global [%0], [%1], 16;" :: "r"(dst), "l"(src))
#define CP_COMMIT() asm volatile("cp.async.commit_group;" ::: "memory")
#define CP_WAIT(n)  asm volatile("cp.async.wait_group %0;" :: "n"(n) : "memory")

#define LDSM4(r0,r1,r2,r3, addr) \
    asm volatile("ldmatrix.sync.aligned.m8n8.x4.shared.b16 {%0,%1,%2,%3}, [%4];" \
        : "=r"(r0),"=r"(r1),"=r"(r2),"=r"(r3) : "r"(addr))

#define LDSM4T(r0,r1,r2,r3, addr) \
    asm volatile("ldmatrix.sync.aligned.m8n8.x4.trans.shared.b16 {%0,%1,%2,%3}, [%4];" \
        : "=r"(r0),"=r"(r1),"=r"(r2),"=r"(r3) : "r"(addr))

__device__ __forceinline__ void mma16(float* c, const uint32_t* a, uint32_t b0, uint32_t b1) {
    asm volatile("mma.sync.aligned.m16n8k16.row.col.f32.f16.f16.f32 "
        "{%0,%1,%2,%3}, {%4,%5,%6,%7}, {%8,%9}, {%0,%1,%2,%3};"
        : "+f"(c[0]), "+f"(c[1]), "+f"(c[2]), "+f"(c[3])
        : "r"(a[0]), "r"(a[1]), "r"(a[2]), "r"(a[3]), "r"(b0), "r"(b1));
}

// ---------------------------------------------------------------------------
// Fused f32 -> f16 conversion of x (4M elems) + 4 weights (1M each).
// ---------------------------------------------------------------------------
__global__ void cvt_all(const float* __restrict__ x,
                        const float* __restrict__ Wq, const float* __restrict__ Wk,
                        const float* __restrict__ Wv, const float* __restrict__ Wo,
                        __half* __restrict__ xh, __half* __restrict__ Wh)
{
    int i = blockIdx.x * blockDim.x + threadIdx.x;     // float4 index, 0..2M-1
    int chunk = i >> 18;
    const float* in;
    __half* out;
    size_t base;
    if (chunk < 4) { in = x; out = xh; base = (size_t)i * 4; }
    else {
        int w = chunk - 4;
        in = (w == 0) ? Wq : (w == 1) ? Wk : (w == 2) ? Wv : Wo;
        out = Wh + (size_t)w * DD * DD;
        base = (size_t)(i & 0x3FFFF) * 4;
    }
    float4 v = *(const float4*)&in[base];
    __half2 h0 = __floats2half2_rn(v.x, v.y);
    __half2 h1 = __floats2half2_rn(v.z, v.w);
    *(uint2*)&out[base] = make_uint2(*(uint32_t*)&h0, *(uint32_t*)&h1);
}

// ---------------------------------------------------------------------------
// Pipelined FP16 GEMM (R10/R12-proven): 128x128x64 tiles, 8 warps, cp.async
// 2-stage (wait->sync->MMA->sync->load), B-fragment double-buffer per k-step.
// MODE 0: fused QKV, RoPE in epilogue for z<2, fp16 out.  MODE 1: f32 out.
// ---------------------------------------------------------------------------
#define BM 128
#define BN 128
#define BK 64
#define ALD 72
#define ATILE_B (BM*ALD*2)          // 18432 bytes
#define STAGE_B (2*ATILE_B)         // A + B = 36864 bytes
#define GEMM_SMEM (2*STAGE_B)       // 73728 bytes
#define NCH (DD/BK)                 // 16 chunks

template<int MODE>
__global__ __launch_bounds__(256, 2) void gemm_f16p(
    const __half* __restrict__ A,
    const __half* __restrict__ Wa, const __half* __restrict__ Wb, const __half* __restrict__ Wc,
    __half* __restrict__ Qh, __half* __restrict__ Kh, __half* __restrict__ Vh,
    float* __restrict__ Cfin, const float* __restrict__ freqs)
{
    const int z = blockIdx.z;
    const __half* W = (z == 0) ? Wa : (z == 1) ? Wb : Wc;

    extern __shared__ char smem[];
    const uint32_t s0 = smem_u32(smem);

    const int tid  = threadIdx.x;
    const int lane = tid & 31, warp = tid >> 5;
    const int g = lane >> 2, t = lane & 3;
    const int lrow = lane & 15, lko = (lane >> 4) * 8;
    const int wm = (warp & 3) * 32;
    const int wn = (warp >> 2) * 64;
    const int row0 = blockIdx.y * BM, col0 = blockIdx.x * BN;

    auto load_stage = [&](int st, int k0) {
        uint32_t base = s0 + st * STAGE_B;
        #pragma unroll
        for (int i = 0; i < 4; i++) {
            int cid = tid + i * 256;          // 0..1023
            int r = cid >> 3, c8 = cid & 7;
            CPA16(base + r*144 + c8*16,           A + (size_t)(row0 + r) * DD + k0 + c8*8);
            CPA16(base + ATILE_B + r*144 + c8*16, W + (size_t)(col0 + r) * DD + k0 + c8*8);
        }
        CP_COMMIT();
    };

    float c[2][8][4] = {};

    load_stage(0, 0);
    load_stage(1, BK);

    for (int ch = 0; ch < NCH; ch++) {
        CP_WAIT(1);
        __syncthreads();

        const uint32_t ab = s0 + (ch & 1) * STAGE_B;
        const uint32_t bb = ab + ATILE_B;

        #pragma unroll
        for (int ks = 0; ks < 4; ks++) {
            const int kk = ks * 16;
            uint32_t af[2][4];
            #pragma unroll
            for (int mi = 0; mi < 2; mi++) {
                uint32_t ad = ab + (uint32_t)((wm + mi*16 + lrow) * ALD + kk + lko) * 2;
                LDSM4(af[mi][0], af[mi][1], af[mi][2], af[mi][3], ad);
            }
            uint32_t bf[2][4];
            LDSM4(bf[0][0], bf[0][1], bf[0][2], bf[0][3],
                  bb + (uint32_t)((wn + lrow) * ALD + kk + lko) * 2);
            #pragma unroll
            for (int n2 = 0; n2 < 4; n2++) {
                if (n2 < 3) {
                    uint32_t bd = bb + (uint32_t)((wn + (n2+1)*16 + lrow) * ALD + kk + lko) * 2;
                    LDSM4(bf[(n2+1)&1][0], bf[(n2+1)&1][1],
                          bf[(n2+1)&1][2], bf[(n2+1)&1][3], bd);
                }
                const uint32_t* b = bf[n2 & 1];
                #pragma unroll
                for (int mi = 0; mi < 2; mi++) {
                    mma16(c[mi][n2*2],   af[mi], b[0], b[2]);
                    mma16(c[mi][n2*2+1], af[mi], b[1], b[3]);
                }
            }
        }
        __syncthreads();
        if (ch + 2 < NCH) load_stage(ch & 1, (ch + 2) * BK);
        else CP_COMMIT();
    }

    #pragma unroll
    for (int mi = 0; mi < 2; mi++) {
        int r = row0 + wm + mi * 16 + g;
        #pragma unroll
        for (int ni = 0; ni < 8; ni++) {
            int cc = col0 + wn + (ni >> 1) * 16 + (ni & 1) * 8 + t * 2;
            float v0 = c[mi][ni][0], v1 = c[mi][ni][1];
            float v2 = c[mi][ni][2], v3 = c[mi][ni][3];
            if (MODE == 1) {
                *(float2*)&Cfin[(size_t)r * DD + cc]       = make_float2(v0, v1);
                *(float2*)&Cfin[(size_t)(r + 8) * DD + cc] = make_float2(v2, v3);
            } else if (z == 2) {
                *(__half2*)&Vh[(size_t)r * DD + cc]       = __floats2half2_rn(v0, v1);
                *(__half2*)&Vh[(size_t)(r + 8) * DD + cc] = __floats2half2_rn(v2, v3);
            } else {
                // fused RoPE: (v0,v1) is an adjacent (even,odd) pair within a head
                __half* C = z ? Kh : Qh;
                int pp = (cc & (HD - 1)) >> 1;
                int l0 = r & (LL - 1), l1 = (r + 8) & (LL - 1);
                float2 f0 = *(const float2*)&freqs[(l0 * (HD/2) + pp) * 2];
                float2 f1 = *(const float2*)&freqs[(l1 * (HD/2) + pp) * 2];
                *(__half2*)&C[(size_t)r * DD + cc] =
                    __floats2half2_rn(v0*f0.x - v1*f0.y, v0*f0.y + v1*f0.x);
                *(__half2*)&C[(size_t)(r + 8) * DD + cc] =
                    __floats2half2_rn(v2*f1.x - v3*f1.y, v2*f1.y + v3*f1.x);
            }
        }
    }
}

// ---------------------------------------------------------------------------
// Flash attention (causal), FA2 register softmax in log2 domain with
// ex2.approx.f16x2: ONE MUFU op per TWO P elements (halves the exp floor),
// and P comes out already packed as fp16 MMA fragments.
// BQ=128, kv-tile 64. 8 warps; warp w owns q-rows w*16..w*16+15, ALL 64 kv.
// ---------------------------------------------------------------------------
#define BQ 128
#define HLD 72
#define QB  (BQ*HLD*2)           // Q tile bytes
#define KVB (64*HLD*2)           // one K or V buffer bytes
#define FL_SMEM_BYTES (QB + 4*KVB)
#define SCL2 0.1803368801111244f   // 0.125 * log2(e)

__global__ __launch_bounds__(256) void flash_f16(
    const __half* __restrict__ Q, const __half* __restrict__ K,
    const __half* __restrict__ V, __half* __restrict__ O)
{
    extern __shared__ __half hsm[];
    const uint32_t qsm  = smem_u32(hsm);
    const uint32_t ksm0 = qsm + QB;           // K0, K1, V0, V1
    const uint32_t vsm0 = qsm + QB + 2*KVB;

    const int tid = threadIdx.x;
    const int lane = tid & 31, warp = tid >> 5;
    const int g = lane >> 2, t = lane & 3;
    const int lrow = lane & 15, lko = (lane >> 4) * 8;
    const int wr = warp * 16;                 // this warp's q-row block
    const int b = blockIdx.y >> 4, h = blockIdx.y & 15;
    const int qi = (int)gridDim.x - 1 - (int)blockIdx.x;   // heavy blocks first
    const int q0 = qi * BQ;
    const size_t headoff = (size_t)b * LL * DD + (size_t)h * HD;

    auto issue_kv = [&](int kt, int buf) {
        const int kv0 = kt * 64;
        uint32_t kb = ksm0 + buf * KVB;
        uint32_t vb = vsm0 + buf * KVB;
        #pragma unroll
        for (int i = 0; i < 4; i++) {
            int cid = tid + i * 256;          // 0..1023
            int isv = cid >> 9;
            int cc  = cid & 511;
            int r = cc >> 3, c8 = cc & 7;
            const __half* src = (isv ? V : K) + headoff + (size_t)(kv0 + r) * DD + c8*8;
            CPA16((isv ? vb : kb) + r*144 + c8*16, src);
        }
    };

    // group 0: Q tile (128 rows) + kv tile 0;  group 1: kv tile 1
    #pragma unroll
    for (int i = 0; i < 4; i++) {
        int cid = tid + i * 256;              // 0..1023
        int r = cid >> 3, c8 = cid & 7;
        CPA16(qsm + r*144 + c8*16, Q + headoff + (size_t)(q0 + r) * DD + c8*8);
    }
    issue_kv(0, 0);
    CP_COMMIT();
    const int ntiles = 2 * qi + 2;
    issue_kv(1, 1);
    CP_COMMIT();

    uint32_t qf[4][4];
    float acc[8][4] = {};
    float m0 = -1e30f, m1 = -1e30f, l0 = 0.f, l1 = 0.f;

    for (int kt = 0; kt < ntiles; kt++) {
        const int kv0 = kt * 64;
        const uint32_t kb = ksm0 + (kt & 1) * KVB;
        const uint32_t vb = vsm0 + (kt & 1) * KVB;
        CP_WAIT(1);
        __syncthreads();

        if (kt == 0) {
            #pragma unroll
            for (int ks = 0; ks < 4; ks++)
                LDSM4(qf[ks][0], qf[ks][1], qf[ks][2], qf[ks][3],
                      qsm + (uint32_t)((wr + lrow) * HLD + ks*16 + lko) * 2);
        }

        // skip warps whose 16 rows are entirely masked (last tile, rows < 64)
        if (!(kt == ntiles - 1 && wr < 64)) {
            // S = Q @ K^T : warp computes 16 x 64
            float sf[8][4] = {};
            #pragma unroll
            for (int ks = 0; ks < 4; ks++) {
                #pragma unroll
                for (int ng = 0; ng < 4; ng++) {
                    uint32_t r0, r1, r2, r3;
                    LDSM4(r0, r1, r2, r3,
                          kb + (uint32_t)((ng*16 + lrow) * HLD + ks*16 + lko) * 2);
                    mma16(sf[ng*2],   qf[ks], r0, r2);
                    mma16(sf[ng*2+1], qf[ks], r1, r3);
                }
            }
            // scale into log2 domain + causal mask (only 2 diagonal tiles)
            const int gr0 = q0 + wr + g, gr1 = gr0 + 8;
            if (kt >= ntiles - 2) {
                #pragma unroll
                for (int nb = 0; nb < 8; nb++) {
                    int gc = kv0 + nb*8 + t*2;
                    sf[nb][0] = (gc     > gr0) ? -1e30f : sf[nb][0]*SCL2;
                    sf[nb][1] = (gc + 1 > gr0) ? -1e30f : sf[nb][1]*SCL2;
                    sf[nb][2] = (gc     > gr1) ? -1e30f : sf[nb][2]*SCL2;
                    sf[nb][3] = (gc + 1 > gr1) ? -1e30f : sf[nb][3]*SCL2;
                }
            } else {
                #pragma unroll
                for (int nb = 0; nb < 8; nb++) {
                    sf[nb][0] *= SCL2; sf[nb][1] *= SCL2;
                    sf[nb][2] *= SCL2; sf[nb][3] *= SCL2;
                }
            }
            // register-resident online softmax (rows g and g+8), log2 domain
            float rmx0 = -1e30f, rmx1 = -1e30f;
            #pragma unroll
            for (int nb = 0; nb < 8; nb++) {
                rmx0 = fmaxf(rmx0, fmaxf(sf[nb][0], sf[nb][1]));
                rmx1 = fmaxf(rmx1, fmaxf(sf[nb][2], sf[nb][3]));
            }
            rmx0 = fmaxf(rmx0, __shfl_xor_sync(0xffffffffu, rmx0, 1));
            rmx0 = fmaxf(rmx0, __shfl_xor_sync(0xffffffffu, rmx0, 2));
            rmx1 = fmaxf(rmx1, __shfl_xor_sync(0xffffffffu, rmx1, 1));
            rmx1 = fmaxf(rmx1, __shfl_xor_sync(0xffffffffu, rmx1, 2));
            float nm0 = fmaxf(m0, rmx0), nm1 = fmaxf(m1, rmx1);
            float al0 = exp2f(m0 - nm0), al1 = exp2f(m1 - nm1);
            m0 = nm0; m1 = nm1;

            // P = 2^(sf - nm) via ex2.approx.f16x2 (2 exps / MUFU op),
            // already packed as fp16 MMA fragments.
            uint32_t pa[8], pb[8];            // rows (g), (g+8) pairs
            float s0 = 0.f, s1 = 0.f;
            #pragma unroll
            for (int nb = 0; nb < 8; nb++) {
                pa[nb] = h2exp2(f2h2(sf[nb][0] - nm0, sf[nb][1] - nm0));
                pb[nb] = h2exp2(f2h2(sf[nb][2] - nm1, sf[nb][3] - nm1));
                float2 u0 = __half22float2(*(__half2*)&pa[nb]);
                float2 u1 = __half22float2(*(__half2*)&pb[nb]);
                s0 += u0.x + u0.y;
                s1 += u1.x + u1.y;
            }
            s0 += __shfl_xor_sync(0xffffffffu, s0, 1);
            s0 += __shfl_xor_sync(0xffffffffu, s0, 2);
            s1 += __shfl_xor_sync(0xffffffffu, s1, 1);
            s1 += __shfl_xor_sync(0xffffffffu, s1, 2);
            l0 = l0 * al0 + s0;
            l1 = l1 * al1 + s1;
            #pragma unroll
            for (int nb = 0; nb < 8; nb++) {
                acc[nb][0] *= al0; acc[nb][1] *= al0;
                acc[nb][2] *= al1; acc[nb][3] *= al1;
            }
            // O += P @ V  (P fragments ready; no packing needed)
            #pragma unroll
            for (int ks = 0; ks < 4; ks++) {
                uint32_t pf[4] = { pa[2*ks], pb[2*ks], pa[2*ks+1], pb[2*ks+1] };
                #pragma unroll
                for (int ng = 0; ng < 4; ng++) {
                    uint32_t r0, r1, r2, r3;   // trans: rows = kv, cols = hd
                    LDSM4T(r0, r1, r2, r3,
                           vb + (uint32_t)((ks*16 + lrow) * HLD + ng*16 + lko) * 2);
                    mma16(acc[ng*2],   pf, r0, r1);
                    mma16(acc[ng*2+1], pf, r2, r3);
                }
            }
        }

        __syncthreads();
        if (kt + 2 < ntiles) issue_kv(kt + 2, kt & 1);
        CP_COMMIT();
    }

    // epilogue (fp16 out)
    {
        int r0r = q0 + wr + g, r1 = r0r + 8;
        float inv0 = 1.f / l0, inv1 = 1.f / l1;
        #pragma unroll
        for (int nb = 0; nb < 8; nb++) {
            int cc = nb*8 + t*2;
            *(__half2*)&O[headoff + (size_t)r0r*DD + cc] =
                __floats2half2_rn(acc[nb][0]*inv0, acc[nb][1]*inv0);
            *(__half2*)&O[headoff + (size_t)r1*DD + cc] =
                __floats2half2_rn(acc[nb][2]*inv1, acc[nb][3]*inv1);
        }
    }
}

// ---------------------------------------------------------------------------
extern "C" void kernel_launch(void* const* d_in, const int* in_sizes, int n_in,
                              void* d_out, int out_size)
{
    const float* x     = (const float*)d_in[0];
    const float* freqs = (const float*)d_in[1];
    // d_in[2] = attention_mask (pure causal; handled structurally)
    const float* Wq = (const float*)d_in[3];
    const float* Wk = (const float*)d_in[4];
    const float* Wv = (const float*)d_in[5];
    const float* Wo = (const float*)d_in[6];
    float* out = (float*)d_out;

    __half *pxh, *pQh, *pKh, *pVh, *pAh, *pWh;
    cudaGetSymbolAddress((void**)&pxh, g_xh);
    cudaGetSymbolAddress((void**)&pQh, g_Qh);
    cudaGetSymbolAddress((void**)&pKh, g_Kh);
    cudaGetSymbolAddress((void**)&pVh, g_Vh);
    cudaGetSymbolAddress((void**)&pAh, g_Ah);
    cudaGetSymbolAddress((void**)&pWh, g_Wh);

    // fused f32 -> f16 conversions (x + 4 weights)
    cvt_all<<<(2*ML*DD/4)/256, 256>>>(x, Wq, Wk, Wv, Wo, pxh, pWh);

    cudaFuncSetAttribute(gemm_f16p<0>, cudaFuncAttributeMaxDynamicSharedMemorySize, GEMM_SMEM);
    cudaFuncSetAttribute(gemm_f16p<1>, cudaFuncAttributeMaxDynamicSharedMemorySize, GEMM_SMEM);

    // Fused QKV projections with RoPE in epilogue (z0->Qh, z1->Kh, z2->Vh)
    gemm_f16p<0><<<dim3(DD/BN, ML/BM, 3), 256, GEMM_SMEM>>>(
        pxh, pWh, pWh + DD*DD, pWh + 2*DD*DD, pQh, pKh, pVh, nullptr, freqs);

    cudaFuncSetAttribute(flash_f16, cudaFuncAttributeMaxDynamicSharedMemorySize, FL_SMEM_BYTES);
    flash_f16<<<dim3(LL/BQ, BB*NH), 256, FL_SMEM_BYTES>>>(pQh, pKh, pVh, pAh);

    // Output projection: f16 A @ Wo^T -> f32 out
    gemm_f16p<1><<<dim3(DD/BN, ML/BM, 1), 256, GEMM_SMEM>>>(
        pAh, pWh + 3*DD*DD, nullptr, nullptr, nullptr, nullptr, nullptr, out, nullptr);
}

// round 16
// speedup vs baseline: 1.5876x; 1.0050x over previous
#include <cuda_runtime.h>
#include <cuda_fp16.h>
#include <cstdint>

// Problem constants: B=2, L=2048, D=1024, H=16, hd=64
#define BB 2
#define LL 2048
#define DD 1024
#define NH 16
#define HD 64
#define ML (BB*LL)          // 4096 rows

// fp16 scratch
static __device__ __half g_xh[ML*DD];
static __device__ __half g_Qh[ML*DD];
static __device__ __half g_Kh[ML*DD];
static __device__ __half g_Vh[ML*DD];
static __device__ __half g_Ah[ML*DD];
static __device__ __half g_Wh[4*DD*DD];

// ---------------------------------------------------------------------------
// helpers
// ---------------------------------------------------------------------------
__device__ __forceinline__ uint32_t smem_u32(const void* p) {
    uint32_t a;
    asm("{ .reg .u64 t; cvta.to.shared.u64 t, %1; cvt.u32.u64 %0, t; }" : "=r"(a) : "l"(p));
    return a;
}

__device__ __forceinline__ uint32_t f2h2(float x, float y) {
    __half2 h = __floats2half2_rn(x, y);
    return *(uint32_t*)&h;
}

// two fp16 exp2's in ONE MUFU op
__device__ __forceinline__ uint32_t h2exp2(uint32_t a) {
    uint32_t d;
    asm("ex2.approx.f16x2 %0, %1;" : "=r"(d) : "r"(a));
    return d;
}

#define CPA16(dst, src) \
    asm volatile("cp.async.cg.shared.global [%0], [%1], 16;" :: "r"(dst), "l"(src))
#define CP_COMMIT() asm volatile("cp.async.commit_group;" ::: "memory")
#define CP_WAIT(n)  asm volatile("cp.async.wait_group %0;" :: "n"(n) : "memory")

#define LDSM4(r0,r1,r2,r3, addr) \
    asm volatile("ldmatrix.sync.aligned.m8n8.x4.shared.b16 {%0,%1,%2,%3}, [%4];" \
        : "=r"(r0),"=r"(r1),"=r"(r2),"=r"(r3) : "r"(addr))

#define LDSM4T(r0,r1,r2,r3, addr) \
    asm volatile("ldmatrix.sync.aligned.m8n8.x4.trans.shared.b16 {%0,%1,%2,%3}, [%4];" \
        : "=r"(r0),"=r"(r1),"=r"(r2),"=r"(r3) : "r"(addr))

__device__ __forceinline__ void mma16(float* c, const uint32_t* a, uint32_t b0, uint32_t b1) {
    asm volatile("mma.sync.aligned.m16n8k16.row.col.f32.f16.f16.f32 "
        "{%0,%1,%2,%3}, {%4,%5,%6,%7}, {%8,%9}, {%0,%1,%2,%3};"
        : "+f"(c[0]), "+f"(c[1]), "+f"(c[2]), "+f"(c[3])
        : "r"(a[0]), "r"(a[1]), "r"(a[2]), "r"(a[3]), "r"(b0), "r"(b1));
}

// ---------------------------------------------------------------------------
// Fused f32 -> f16 conversion of x (4M elems) + 4 weights (1M each).
// ---------------------------------------------------------------------------
__global__ void cvt_all(const float* __restrict__ x,
                        const float* __restrict__ Wq, const float* __restrict__ Wk,
                        const float* __restrict__ Wv, const float* __restrict__ Wo,
                        __half* __restrict__ xh, __half* __restrict__ Wh)
{
    int i = blockIdx.x * blockDim.x + threadIdx.x;     // float4 index, 0..2M-1
    int chunk = i >> 18;
    const float* in;
    __half* out;
    size_t base;
    if (chunk < 4) { in = x; out = xh; base = (size_t)i * 4; }
    else {
        int w = chunk - 4;
        in = (w == 0) ? Wq : (w == 1) ? Wk : (w == 2) ? Wv : Wo;
        out = Wh + (size_t)w * DD * DD;
        base = (size_t)(i & 0x3FFFF) * 4;
    }
    float4 v = *(const float4*)&in[base];
    __half2 h0 = __floats2half2_rn(v.x, v.y);
    __half2 h1 = __floats2half2_rn(v.z, v.w);
    *(uint2*)&out[base] = make_uint2(*(uint32_t*)&h0, *(uint32_t*)&h1);
}

// ---------------------------------------------------------------------------
// Pipelined FP16 GEMM (R10/R12-proven): 128x128x64 tiles, 8 warps, cp.async
// 2-stage (wait->sync->MMA->sync->load), B-fragment double-buffer per k-step.
// MODE 0: fused QKV, RoPE in epilogue for z<2, fp16 out.  MODE 1: f32 out.
// ---------------------------------------------------------------------------
#define BM 128
#define BN 128
#define BK 64
#define ALD 72
#define ATILE_B (BM*ALD*2)          // 18432 bytes
#define STAGE_B (2*ATILE_B)         // A + B = 36864 bytes
#define GEMM_SMEM (2*STAGE_B)       // 73728 bytes
#define NCH (DD/BK)                 // 16 chunks

template<int MODE>
__global__ __launch_bounds__(256, 2) void gemm_f16p(
    const __half* __restrict__ A,
    const __half* __restrict__ Wa, const __half* __restrict__ Wb, const __half* __restrict__ Wc,
    __half* __restrict__ Qh, __half* __restrict__ Kh, __half* __restrict__ Vh,
    float* __restrict__ Cfin, const float* __restrict__ freqs)
{
    const int z = blockIdx.z;
    const __half* W = (z == 0) ? Wa : (z == 1) ? Wb : Wc;

    extern __shared__ char smem[];
    const uint32_t s0 = smem_u32(smem);

    const int tid  = threadIdx.x;
    const int lane = tid & 31, warp = tid >> 5;
    const int g = lane >> 2, t = lane & 3;
    const int lrow = lane & 15, lko = (lane >> 4) * 8;
    const int wm = (warp & 3) * 32;
    const int wn = (warp >> 2) * 64;
    const int row0 = blockIdx.y * BM, col0 = blockIdx.x * BN;

    auto load_stage = [&](int st, int k0) {
        uint32_t base = s0 + st * STAGE_B;
        #pragma unroll
        for (int i = 0; i < 4; i++) {
            int cid = tid + i * 256;          // 0..1023
            int r = cid >> 3, c8 = cid & 7;
            CPA16(base + r*144 + c8*16,           A + (size_t)(row0 + r) * DD + k0 + c8*8);
            CPA16(base + ATILE_B + r*144 + c8*16, W + (size_t)(col0 + r) * DD + k0 + c8*8);
        }
        CP_COMMIT();
    };

    float c[2][8][4] = {};

    load_stage(0, 0);
    load_stage(1, BK);

    for (int ch = 0; ch < NCH; ch++) {
        CP_WAIT(1);
        __syncthreads();

        const uint32_t ab = s0 + (ch & 1) * STAGE_B;
        const uint32_t bb = ab + ATILE_B;

        #pragma unroll
        for (int ks = 0; ks < 4; ks++) {
            const int kk = ks * 16;
            uint32_t af[2][4];
            #pragma unroll
            for (int mi = 0; mi < 2; mi++) {
                uint32_t ad = ab + (uint32_t)((wm + mi*16 + lrow) * ALD + kk + lko) * 2;
                LDSM4(af[mi][0], af[mi][1], af[mi][2], af[mi][3], ad);
            }
            uint32_t bf[2][4];
            LDSM4(bf[0][0], bf[0][1], bf[0][2], bf[0][3],
                  bb + (uint32_t)((wn + lrow) * ALD + kk + lko) * 2);
            #pragma unroll
            for (int n2 = 0; n2 < 4; n2++) {
                if (n2 < 3) {
                    uint32_t bd = bb + (uint32_t)((wn + (n2+1)*16 + lrow) * ALD + kk + lko) * 2;
                    LDSM4(bf[(n2+1)&1][0], bf[(n2+1)&1][1],
                          bf[(n2+1)&1][2], bf[(n2+1)&1][3], bd);
                }
                const uint32_t* b = bf[n2 & 1];
                #pragma unroll
                for (int mi = 0; mi < 2; mi++) {
                    mma16(c[mi][n2*2],   af[mi], b[0], b[2]);
                    mma16(c[mi][n2*2+1], af[mi], b[1], b[3]);
                }
            }
        }
        __syncthreads();
        if (ch + 2 < NCH) load_stage(ch & 1, (ch + 2) * BK);
        else CP_COMMIT();
    }

    #pragma unroll
    for (int mi = 0; mi < 2; mi++) {
        int r = row0 + wm + mi * 16 + g;
        #pragma unroll
        for (int ni = 0; ni < 8; ni++) {
            int cc = col0 + wn + (ni >> 1) * 16 + (ni & 1) * 8 + t * 2;
            float v0 = c[mi][ni][0], v1 = c[mi][ni][1];
            float v2 = c[mi][ni][2], v3 = c[mi][ni][3];
            if (MODE == 1) {
                *(float2*)&Cfin[(size_t)r * DD + cc]       = make_float2(v0, v1);
                *(float2*)&Cfin[(size_t)(r + 8) * DD + cc] = make_float2(v2, v3);
            } else if (z == 2) {
                *(__half2*)&Vh[(size_t)r * DD + cc]       = __floats2half2_rn(v0, v1);
                *(__half2*)&Vh[(size_t)(r + 8) * DD + cc] = __floats2half2_rn(v2, v3);
            } else {
                // fused RoPE: (v0,v1) is an adjacent (even,odd) pair within a head
                __half* C = z ? Kh : Qh;
                int pp = (cc & (HD - 1)) >> 1;
                int l0 = r & (LL - 1), l1 = (r + 8) & (LL - 1);
                float2 f0 = *(const float2*)&freqs[(l0 * (HD/2) + pp) * 2];
                float2 f1 = *(const float2*)&freqs[(l1 * (HD/2) + pp) * 2];
                *(__half2*)&C[(size_t)r * DD + cc] =
                    __floats2half2_rn(v0*f0.x - v1*f0.y, v0*f0.y + v1*f0.x);
                *(__half2*)&C[(size_t)(r + 8) * DD + cc] =
                    __floats2half2_rn(v2*f1.x - v3*f1.y, v2*f1.y + v3*f1.x);
            }
        }
    }
}

// ---------------------------------------------------------------------------
// Flash attention (causal), FA2 register softmax, log2 domain, f16x2 exp.
// R14: (1) l kept as PER-THREAD partial, quad-reduced once in the epilogue
//      (saves 2 shfl per tile, exact); (2) running max in RAW S domain,
//      exp argument via single FFMA (saves 32 FMUL/tile, merges subtract).
// BQ=128, kv-tile 64. 8 warps; warp w owns q-rows w*16..w*16+15, ALL 64 kv.
// ---------------------------------------------------------------------------
#define BQ 128
#define HLD 72
#define QB  (BQ*HLD*2)           // Q tile bytes
#define KVB (64*HLD*2)           // one K or V buffer bytes
#define FL_SMEM_BYTES (QB + 4*KVB)
#define SCL2 0.1803368801111244f   // 0.125 * log2(e)

__global__ __launch_bounds__(256) void flash_f16(
    const __half* __restrict__ Q, const __half* __restrict__ K,
    const __half* __restrict__ V, __half* __restrict__ O)
{
    extern __shared__ __half hsm[];
    const uint32_t qsm  = smem_u32(hsm);
    const uint32_t ksm0 = qsm + QB;           // K0, K1, V0, V1
    const uint32_t vsm0 = qsm + QB + 2*KVB;

    const int tid = threadIdx.x;
    const int lane = tid & 31, warp = tid >> 5;
    const int g = lane >> 2, t = lane & 3;
    const int lrow = lane & 15, lko = (lane >> 4) * 8;
    const int wr = warp * 16;                 // this warp's q-row block
    const int b = blockIdx.y >> 4, h = blockIdx.y & 15;
    const int qi = (int)gridDim.x - 1 - (int)blockIdx.x;   // heavy blocks first
    const int q0 = qi * BQ;
    const size_t headoff = (size_t)b * LL * DD + (size_t)h * HD;

    auto issue_kv = [&](int kt, int buf) {
        const int kv0 = kt * 64;
        uint32_t kb = ksm0 + buf * KVB;
        uint32_t vb = vsm0 + buf * KVB;
        #pragma unroll
        for (int i = 0; i < 4; i++) {
            int cid = tid + i * 256;          // 0..1023
            int isv = cid >> 9;
            int cc  = cid & 511;
            int r = cc >> 3, c8 = cc & 7;
            const __half* src = (isv ? V : K) + headoff + (size_t)(kv0 + r) * DD + c8*8;
            CPA16((isv ? vb : kb) + r*144 + c8*16, src);
        }
    };

    // group 0: Q tile (128 rows) + kv tile 0;  group 1: kv tile 1
    #pragma unroll
    for (int i = 0; i < 4; i++) {
        int cid = tid + i * 256;              // 0..1023
        int r = cid >> 3, c8 = cid & 7;
        CPA16(qsm + r*144 + c8*16, Q + headoff + (size_t)(q0 + r) * DD + c8*8);
    }
    issue_kv(0, 0);
    CP_COMMIT();
    const int ntiles = 2 * qi + 2;
    issue_kv(1, 1);
    CP_COMMIT();

    uint32_t qf[4][4];
    float acc[8][4] = {};
    float m0 = -1e30f, m1 = -1e30f;   // running max, RAW S domain
    float l0 = 0.f, l1 = 0.f;         // PER-THREAD partial denominators

    for (int kt = 0; kt < ntiles; kt++) {
        const int kv0 = kt * 64;
        const uint32_t kb = ksm0 + (kt & 1) * KVB;
        const uint32_t vb = vsm0 + (kt & 1) * KVB;
        CP_WAIT(1);
        __syncthreads();

        if (kt == 0) {
            #pragma unroll
            for (int ks = 0; ks < 4; ks++)
                LDSM4(qf[ks][0], qf[ks][1], qf[ks][2], qf[ks][3],
                      qsm + (uint32_t)((wr + lrow) * HLD + ks*16 + lko) * 2);
        }

        // skip warps whose 16 rows are entirely masked (last tile, rows < 64)
        if (!(kt == ntiles - 1 && wr < 64)) {
            // S = Q @ K^T : warp computes 16 x 64  (RAW domain, no scaling)
            float sf[8][4] = {};
            #pragma unroll
            for (int ks = 0; ks < 4; ks++) {
                #pragma unroll
                for (int ng = 0; ng < 4; ng++) {
                    uint32_t r0, r1, r2, r3;
                    LDSM4(r0, r1, r2, r3,
                          kb + (uint32_t)((ng*16 + lrow) * HLD + ks*16 + lko) * 2);
                    mma16(sf[ng*2],   qf[ks], r0, r2);
                    mma16(sf[ng*2+1], qf[ks], r1, r3);
                }
            }
            // causal mask only (raw domain; only 2 diagonal tiles)
            if (kt >= ntiles - 2) {
                const int gr0 = q0 + wr + g, gr1 = gr0 + 8;
                #pragma unroll
                for (int nb = 0; nb < 8; nb++) {
                    int gc = kv0 + nb*8 + t*2;
                    if (gc     > gr0) sf[nb][0] = -1e30f;
                    if (gc + 1 > gr0) sf[nb][1] = -1e30f;
                    if (gc     > gr1) sf[nb][2] = -1e30f;
                    if (gc + 1 > gr1) sf[nb][3] = -1e30f;
                }
            }
            // quad max (raw domain; scale is positive => monotone)
            float rmx0 = -1e30f, rmx1 = -1e30f;
            #pragma unroll
            for (int nb = 0; nb < 8; nb++) {
                rmx0 = fmaxf(rmx0, fmaxf(sf[nb][0], sf[nb][1]));
                rmx1 = fmaxf(rmx1, fmaxf(sf[nb][2], sf[nb][3]));
            }
            rmx0 = fmaxf(rmx0, __shfl_xor_sync(0xffffffffu, rmx0, 1));
            rmx0 = fmaxf(rmx0, __shfl_xor_sync(0xffffffffu, rmx0, 2));
            rmx1 = fmaxf(rmx1, __shfl_xor_sync(0xffffffffu, rmx1, 1));
            rmx1 = fmaxf(rmx1, __shfl_xor_sync(0xffffffffu, rmx1, 2));
            float nm0 = fmaxf(m0, rmx0), nm1 = fmaxf(m1, rmx1);
            float al0 = exp2f((m0 - nm0) * SCL2), al1 = exp2f((m1 - nm1) * SCL2);
            m0 = nm0; m1 = nm1;
            const float c0 = -nm0 * SCL2, c1 = -nm1 * SCL2;

            // P = 2^(sf*SCL2 - nm*SCL2) via FFMA + ex2.approx.f16x2;
            // fragments come out packed for the PV MMA.
            uint32_t pa[8], pb[8];
            float s0 = 0.f, s1 = 0.f;     // LOCAL sums (no shfl)
            #pragma unroll
            for (int nb = 0; nb < 8; nb++) {
                pa[nb] = h2exp2(f2h2(fmaf(sf[nb][0], SCL2, c0),
                                     fmaf(sf[nb][1], SCL2, c0)));
                pb[nb] = h2exp2(f2h2(fmaf(sf[nb][2], SCL2, c1),
                                     fmaf(sf[nb][3], SCL2, c1)));
                float2 u0 = __half22float2(*(__half2*)&pa[nb]);
                float2 u1 = __half22float2(*(__half2*)&pb[nb]);
                s0 += u0.x + u0.y;
                s1 += u1.x + u1.y;
            }
            l0 = l0 * al0 + s0;
            l1 = l1 * al1 + s1;
            #pragma unroll
            for (int nb = 0; nb < 8; nb++) {
                acc[nb][0] *= al0; acc[nb][1] *= al0;
                acc[nb][2] *= al1; acc[nb][3] *= al1;
            }
            // O += P @ V
            #pragma unroll
            for (int ks = 0; ks < 4; ks++) {
                uint32_t pf[4] = { pa[2*ks], pb[2*ks], pa[2*ks+1], pb[2*ks+1] };
                #pragma unroll
                for (int ng = 0; ng < 4; ng++) {
                    uint32_t r0, r1, r2, r3;   // trans: rows = kv, cols = hd
                    LDSM4T(r0, r1, r2, r3,
                           vb + (uint32_t)((ks*16 + lrow) * HLD + ng*16 + lko) * 2);
                    mma16(acc[ng*2],   pf, r0, r1);
                    mma16(acc[ng*2+1], pf, r2, r3);
                }
            }
        }

        __syncthreads();
        if (kt + 2 < ntiles) issue_kv(kt + 2, kt & 1);
        CP_COMMIT();
    }

    // epilogue: quad-reduce the deferred denominators ONCE, then store
    {
        l0 += __shfl_xor_sync(0xffffffffu, l0, 1);
        l0 += __shfl_xor_sync(0xffffffffu, l0, 2);
        l1 += __shfl_xor_sync(0xffffffffu, l1, 1);
        l1 += __shfl_xor_sync(0xffffffffu, l1, 2);
        int r0r = q0 + wr + g, r1 = r0r + 8;
        float inv0 = 1.f / l0, inv1 = 1.f / l1;
        #pragma unroll
        for (int nb = 0; nb < 8; nb++) {
            int cc = nb*8 + t*2;
            *(__half2*)&O[headoff + (size_t)r0r*DD + cc] =
                __floats2half2_rn(acc[nb][0]*inv0, acc[nb][1]*inv0);
            *(__half2*)&O[headoff + (size_t)r1*DD + cc] =
                __floats2half2_rn(acc[nb][2]*inv1, acc[nb][3]*inv1);
        }
    }
}

// ---------------------------------------------------------------------------
extern "C" void kernel_launch(void* const* d_in, const int* in_sizes, int n_in,
                              void* d_out, int out_size)
{
    const float* x     = (const float*)d_in[0];
    const float* freqs = (const float*)d_in[1];
    // d_in[2] = attention_mask (pure causal; handled structurally)
    const float* Wq = (const float*)d_in[3];
    const float* Wk = (const float*)d_in[4];
    const float* Wv = (const float*)d_in[5];
    const float* Wo = (const float*)d_in[6];
    float* out = (float*)d_out;

    __half *pxh, *pQh, *pKh, *pVh, *pAh, *pWh;
    cudaGetSymbolAddress((void**)&pxh, g_xh);
    cudaGetSymbolAddress((void**)&pQh, g_Qh);
    cudaGetSymbolAddress((void**)&pKh, g_Kh);
    cudaGetSymbolAddress((void**)&pVh, g_Vh);
    cudaGetSymbolAddress((void**)&pAh, g_Ah);
    cudaGetSymbolAddress((void**)&pWh, g_Wh);

    // fused f32 -> f16 conversions (x + 4 weights)
    cvt_all<<<(2*ML*DD/4)/256, 256>>>(x, Wq, Wk, Wv, Wo, pxh, pWh);

    cudaFuncSetAttribute(gemm_f16p<0>, cudaFuncAttributeMaxDynamicSharedMemorySize, GEMM_SMEM);
    cudaFuncSetAttribute(gemm_f16p<1>, cudaFuncAttributeMaxDynamicSharedMemorySize, GEMM_SMEM);

    // Fused QKV projections with RoPE in epilogue (z0->Qh, z1->Kh, z2->Vh)
    gemm_f16p<0><<<dim3(DD/BN, ML/BM, 3), 256, GEMM_SMEM>>>(
        pxh, pWh, pWh + DD*DD, pWh + 2*DD*DD, pQh, pKh, pVh, nullptr, freqs);

    cudaFuncSetAttribute(flash_f16, cudaFuncAttributeMaxDynamicSharedMemorySize, FL_SMEM_BYTES);
    flash_f16<<<dim3(LL/BQ, BB*NH), 256, FL_SMEM_BYTES>>>(pQh, pKh, pVh, pAh);

    // Output projection: f16 A @ Wo^T -> f32 out
    gemm_f16p<1><<<dim3(DD/BN, ML/BM, 1), 256, GEMM_SMEM>>>(
        pAh, pWh + 3*DD*DD, nullptr, nullptr, nullptr, nullptr, nullptr, out, nullptr);
}